// round 9
// baseline (speedup 1.0000x reference)
#include <cuda_runtime.h>
#include <cuda_bf16.h>
#include <cstdint>

#define BATCH   8
#define NPTS    4096
#define CIN_PTS 64
#define NPOINT  1024
#define NCENT   (BATCH * NPOINT)   // 8192
#define FEAT_W  320
#define NTH     512                // threads per MLP block

// ---------------- device scratch ----------------
__device__ float g_new_xyz[NCENT * 3];
__device__ int   g_idx0[NCENT * 16];
__device__ int   g_idx1[NCENT * 32];
__device__ int   g_idx2[NCENT * 128];

__host__ __device__ constexpr int cmax3i(int a, int b, int c) {
    return a > b ? (a > c ? a : c) : (b > c ? b : c);
}
__host__ __device__ constexpr int cmax2i(int a, int b) { return a > b ? a : b; }
// pad to multiple of 8 with (pad mod 32) in {8,24}  -> conflict-free LDS.64 strides
__host__ __device__ constexpr int KPAD(int k) {
    int m = (k + 7) & ~7;
    int r = m & 31;
    return (r == 8 || r == 24) ? m : m + 8;
}

#define S_IN (KPAD(67))   // 72

// k-permutation within each 8-column block: logical k -> storage j
__device__ __forceinline__ int kperm(int k) { return ((k & 3) << 1) | ((k >> 2) & 1); }
// inverse: storage j -> logical k
__device__ __forceinline__ int kinv(int j)  { return (j >> 1) | ((j & 1) << 2); }

// =====================================================================
// FPS: one block per batch, 256 threads x 16 register-resident points.
// =====================================================================
__global__ __launch_bounds__(256) void fps_kernel(const float* __restrict__ xyz,
                                                  float* __restrict__ out_newxyz)
{
    int b = blockIdx.x;
    extern __shared__ float sm[];
    float* sx = sm;
    float* sy = sm + NPTS;
    float* sz = sm + 2 * NPTS;
    __shared__ unsigned long long skey[3];

    const float* base = xyz + (size_t)b * NPTS * 3;
    float px[16], py[16], pz[16], pd[16];
    #pragma unroll
    for (int r = 0; r < 16; r++) {
        int p = threadIdx.x + r * 256;
        float x = base[p * 3 + 0];
        float y = base[p * 3 + 1];
        float z = base[p * 3 + 2];
        sx[p] = x; sy[p] = y; sz[p] = z;
        px[r] = x; py[r] = y; pz[r] = z;
        pd[r] = 1e10f;
    }
    if (threadIdx.x == 0) {
        skey[0] = 0xFFFFFFFFull;   // decodes to index 0
        skey[1] = 0ull;
        skey[2] = 0ull;
    }
    __syncthreads();

    int lane = threadIdx.x & 31;

    for (int it = 0; it < NPOINT; it++) {
        int cur = it % 3, nxt = (it + 1) % 3, rst = (it + 2) % 3;
        unsigned int low = (unsigned int)skey[cur];
        int far = (int)(0xFFFFFFFFu - low);

        if (threadIdx.x == 0) {
            float fx = sx[far], fy = sy[far], fz = sz[far];
            int row = b * NPOINT + it;
            out_newxyz[row * 3 + 0] = fx;
            out_newxyz[row * 3 + 1] = fy;
            out_newxyz[row * 3 + 2] = fz;
            g_new_xyz[row * 3 + 0] = fx;
            g_new_xyz[row * 3 + 1] = fy;
            g_new_xyz[row * 3 + 2] = fz;
            skey[rst] = 0ull;
        }
        float cx = sx[far], cy = sy[far], cz = sz[far];

        float bv = -1.0f;
        int   bi = 0;
        #pragma unroll
        for (int r = 0; r < 16; r++) {
            float dx = px[r] - cx;
            float dy = py[r] - cy;
            float dz = pz[r] - cz;
            float d = __fadd_rn(__fadd_rn(__fmul_rn(dx, dx), __fmul_rn(dy, dy)),
                                __fmul_rn(dz, dz));
            float nd = fminf(pd[r], d);
            pd[r] = nd;
            if (nd > bv) { bv = nd; bi = threadIdx.x + r * 256; }
        }
        #pragma unroll
        for (int off = 16; off >= 1; off >>= 1) {
            float ov = __shfl_down_sync(0xffffffffu, bv, off);
            int   oi = __shfl_down_sync(0xffffffffu, bi, off);
            if (ov > bv || (ov == bv && oi < bi)) { bv = ov; bi = oi; }
        }
        if (lane == 0) {
            unsigned long long key =
                ((unsigned long long)__float_as_uint(bv) << 32) |
                (unsigned long long)(0xFFFFFFFFu - (unsigned int)bi);
            atomicMax(&skey[nxt], key);
        }
        __syncthreads();
    }
}

// =====================================================================
// Fused ball query (3 radii, one smem-staged scan). Warp per center.
// =====================================================================
__global__ __launch_bounds__(256) void bq_fused_kernel(const float* __restrict__ xyz,
                                                       int* __restrict__ o0,
                                                       int* __restrict__ o1,
                                                       int* __restrict__ o2)
{
    extern __shared__ float sm[];
    float* sx = sm;
    float* sy = sm + NPTS;
    float* sz = sm + 2 * NPTS;

    int wid  = threadIdx.x >> 5;
    int lane = threadIdx.x & 31;
    int gw   = blockIdx.x * 8 + wid;
    int b    = gw >> 10;

    const float* base = xyz + (size_t)b * NPTS * 3;
    for (int t = threadIdx.x; t < NPTS * 3; t += 256) {
        int p = t / 3, c = t - p * 3;
        float v = base[t];
        (c == 0 ? sx : (c == 1 ? sy : sz))[p] = v;
    }
    __syncthreads();

    const float r2_0 = (float)(0.1 * 0.1);
    const float r2_1 = (float)(0.2 * 0.2);
    const float r2_2 = (float)(0.4 * 0.4);

    float cx = g_new_xyz[gw * 3 + 0];
    float cy = g_new_xyz[gw * 3 + 1];
    float cz = g_new_xyz[gw * 3 + 2];

    int* p0 = o0 + (size_t)gw * 16;
    int* p1 = o1 + (size_t)gw * 32;
    int* p2 = o2 + (size_t)gw * 128;

    int c0 = 0, c1 = 0, c2 = 0;
    int f0 = -1, f1 = -1, f2 = -1;
    unsigned lmask = (1u << lane) - 1u;

    for (int s = 0; s < NPTS; s += 32) {
        int p = s + lane;
        float dx = sx[p] - cx;
        float dy = sy[p] - cy;
        float dz = sz[p] - cz;
        float d2 = __fadd_rn(__fadd_rn(__fmul_rn(dx, dx), __fmul_rn(dy, dy)),
                             __fmul_rn(dz, dz));
        bool h0 = d2 < r2_0, h1 = d2 < r2_1, h2 = d2 < r2_2;
        unsigned m0 = __ballot_sync(0xffffffffu, h0);
        unsigned m1 = __ballot_sync(0xffffffffu, h1);
        unsigned m2 = __ballot_sync(0xffffffffu, h2);
        if (m0) {
            if (f0 < 0) f0 = s + (__ffs(m0) - 1);
            if (h0) { int pos = c0 + __popc(m0 & lmask); if (pos < 16) p0[pos] = p; }
            c0 += __popc(m0);
        }
        if (m1) {
            if (f1 < 0) f1 = s + (__ffs(m1) - 1);
            if (h1) { int pos = c1 + __popc(m1 & lmask); if (pos < 32) p1[pos] = p; }
            c1 += __popc(m1);
        }
        if (m2) {
            if (f2 < 0) f2 = s + (__ffs(m2) - 1);
            if (h2) { int pos = c2 + __popc(m2 & lmask); if (pos < 128) p2[pos] = p; }
            c2 += __popc(m2);
        }
        if (c0 >= 16 && c1 >= 32 && c2 >= 128) break;
    }
    for (int pos = c0 + lane; pos < 16; pos += 32) p0[pos] = f0;
    for (int pos = c1 + lane; pos < 32; pos += 32) p1[pos] = f1;
    for (int pos = c2 + lane; pos < 128; pos += 32) p2[pos] = f2;
}

// =====================================================================
// tf32 mma building blocks. 512 threads: 4 m-warps (w>>2) x 4 n-warps (w&3).
// All smem buffers hold tf32 bits in k-pair-PERMUTED layout:
//   within each 8-col block, logical k stored at kperm(k), so fragment
//   pairs (k, k+4) are adjacent -> LDS.64. Weights stored TRANSPOSED
//   [N][KP] so B fragments are also one LDS.64.
// =====================================================================
__device__ __forceinline__ uint32_t f2tf32(float f) {
    uint32_t r; asm("cvt.rna.tf32.f32 %0, %1;" : "=r"(r) : "f"(f)); return r;
}
__device__ __forceinline__ float f2tf32f(float f) {
    return __uint_as_float(f2tf32(f));
}

__device__ __forceinline__ void mma_tf32(float* d, const uint32_t* a, const uint32_t* b) {
    asm volatile("mma.sync.aligned.m16n8k8.row.col.f32.tf32.tf32.f32 "
                 "{%0,%1,%2,%3},{%4,%5,%6,%7},{%8,%9},{%0,%1,%2,%3};"
                 : "+f"(d[0]), "+f"(d[1]), "+f"(d[2]), "+f"(d[3])
                 : "r"(a[0]), "r"(a[1]), "r"(a[2]), "r"(a[3]),
                   "r"(b[0]), "r"(b[1]));
}

// A: [128][SA] permuted; W: [N][KP] transposed+permuted (chunk rows at sW).
template<int KSTEPS, int SA, int KP, int NT>
__device__ __forceinline__ void mma_accum(const float* __restrict__ sA, int kOff,
                                          const float* __restrict__ sW,
                                          float (&acc)[2][NT][4])
{
    int lane = threadIdx.x & 31;
    int w    = threadIdx.x >> 5;
    int g    = lane >> 2;
    int tg   = lane & 3;
    int m0   = (w >> 2) * 32;
    int n0   = (w & 3) * (NT * 8);

    #pragma unroll
    for (int ks = 0; ks < KSTEPS; ks++) {
        int k0 = ks * 8;
        uint32_t a[2][4];
        #pragma unroll
        for (int mt = 0; mt < 2; mt++) {
            const float* Ab = sA + (size_t)(m0 + 16 * mt) * SA + kOff + k0 + 2 * tg;
            float2 lo = *reinterpret_cast<const float2*>(Ab + (size_t)g * SA);
            float2 hi = *reinterpret_cast<const float2*>(Ab + (size_t)(g + 8) * SA);
            a[mt][0] = __float_as_uint(lo.x);
            a[mt][2] = __float_as_uint(lo.y);
            a[mt][1] = __float_as_uint(hi.x);
            a[mt][3] = __float_as_uint(hi.y);
        }
        #pragma unroll
        for (int nt = 0; nt < NT; nt++) {
            const float* Wb = sW + (size_t)(n0 + 8 * nt + g) * KP + k0 + 2 * tg;
            float2 bv = *reinterpret_cast<const float2*>(Wb);
            uint32_t bfr[2];
            bfr[0] = __float_as_uint(bv.x);
            bfr[1] = __float_as_uint(bv.y);
            mma_tf32(acc[0][nt], a[0], bfr);
            mma_tf32(acc[1][nt], a[1], bfr);
        }
    }
}

// writes tf32(relu(acc+bias)) into sOut in PERMUTED layout
template<int NT, int SOUT>
__device__ __forceinline__ void epi_relu(float (&acc)[2][NT][4],
                                         const float* __restrict__ gBias,
                                         float* __restrict__ sOut)
{
    int lane = threadIdx.x & 31;
    int w    = threadIdx.x >> 5;
    int g    = lane >> 2;
    int tg   = lane & 3;
    int m0   = (w >> 2) * 32;
    int n0   = (w & 3) * (NT * 8);
    int j0   = kperm(2 * tg);
    int j1   = kperm(2 * tg + 1);
    #pragma unroll
    for (int mt = 0; mt < 2; mt++)
        #pragma unroll
        for (int nt = 0; nt < NT; nt++) {
            int row = m0 + 16 * mt + g;
            int cb  = n0 + 8 * nt;           // 8-block base (storage==logical)
            int col = cb + 2 * tg;           // logical column for bias
            float b0v = gBias[col], b1v = gBias[col + 1];
            sOut[row * SOUT + cb + j0]       = f2tf32f(fmaxf(acc[mt][nt][0] + b0v, 0.0f));
            sOut[row * SOUT + cb + j1]       = f2tf32f(fmaxf(acc[mt][nt][1] + b1v, 0.0f));
            sOut[(row + 8) * SOUT + cb + j0] = f2tf32f(fmaxf(acc[mt][nt][2] + b0v, 0.0f));
            sOut[(row + 8) * SOUT + cb + j1] = f2tf32f(fmaxf(acc[mt][nt][3] + b1v, 0.0f));
        }
}

template<int NT, int SEG>
__device__ __forceinline__ void epi_final(float (&acc)[2][NT][4],
                                          const float* __restrict__ gBias,
                                          int* __restrict__ sMaxI,
                                          float* __restrict__ outF, int centerBase)
{
    int lane = threadIdx.x & 31;
    int w    = threadIdx.x >> 5;
    int g    = lane >> 2;
    int tg   = lane & 3;
    int n0   = (w & 3) * (NT * 8);

    if (SEG == 128) {
        #pragma unroll
        for (int nt = 0; nt < NT; nt++) {
            int col = n0 + 8 * nt + 2 * tg;
            float v0 = fmaxf(fmaxf(acc[0][nt][0], acc[0][nt][2]),
                             fmaxf(acc[1][nt][0], acc[1][nt][2]));
            float v1 = fmaxf(fmaxf(acc[0][nt][1], acc[0][nt][3]),
                             fmaxf(acc[1][nt][1], acc[1][nt][3]));
            v0 = fmaxf(v0 + gBias[col], 0.0f);
            v1 = fmaxf(v1 + gBias[col + 1], 0.0f);
            #pragma unroll
            for (int off = 4; off < 32; off <<= 1) {
                v0 = fmaxf(v0, __shfl_xor_sync(0xffffffffu, v0, off));
                v1 = fmaxf(v1, __shfl_xor_sync(0xffffffffu, v1, off));
            }
            if (g == 0) {
                atomicMax(&sMaxI[col],     __float_as_int(v0));
                atomicMax(&sMaxI[col + 1], __float_as_int(v1));
            }
        }
    } else if (SEG == 32) {
        int center = centerBase + (w >> 2);
        #pragma unroll
        for (int nt = 0; nt < NT; nt++) {
            int col = n0 + 8 * nt + 2 * tg;
            float v0 = fmaxf(fmaxf(acc[0][nt][0], acc[0][nt][2]),
                             fmaxf(acc[1][nt][0], acc[1][nt][2]));
            float v1 = fmaxf(fmaxf(acc[0][nt][1], acc[0][nt][3]),
                             fmaxf(acc[1][nt][1], acc[1][nt][3]));
            #pragma unroll
            for (int off = 4; off < 32; off <<= 1) {
                v0 = fmaxf(v0, __shfl_xor_sync(0xffffffffu, v0, off));
                v1 = fmaxf(v1, __shfl_xor_sync(0xffffffffu, v1, off));
            }
            if (g == 0) {
                float* op = outF + (size_t)center * FEAT_W;
                op[col]     = fmaxf(v0 + gBias[col], 0.0f);
                op[col + 1] = fmaxf(v1 + gBias[col + 1], 0.0f);
            }
        }
    } else { // SEG == 16: each m-tile (mt) is one center
        #pragma unroll
        for (int mt = 0; mt < 2; mt++) {
            int center = centerBase + (w >> 2) * 2 + mt;
            #pragma unroll
            for (int nt = 0; nt < NT; nt++) {
                int col = n0 + 8 * nt + 2 * tg;
                float v0 = fmaxf(acc[mt][nt][0], acc[mt][nt][2]);
                float v1 = fmaxf(acc[mt][nt][1], acc[mt][nt][3]);
                #pragma unroll
                for (int off = 4; off < 32; off <<= 1) {
                    v0 = fmaxf(v0, __shfl_xor_sync(0xffffffffu, v0, off));
                    v1 = fmaxf(v1, __shfl_xor_sync(0xffffffffu, v1, off));
                }
                if (g == 0) {
                    float* op = outF + (size_t)center * FEAT_W;
                    op[col]     = fmaxf(v0 + gBias[col], 0.0f);
                    op[col + 1] = fmaxf(v1 + gBias[col + 1], 0.0f);
                }
            }
        }
    }
}

// stage a weight chunk TRANSPOSED into [NC][KP], k-permuted, tf32-converted.
// gW points at chunk row 0 of original [K][NC] row-major weights.
template<int NC, int KP>
__device__ __forceinline__ void stage_wt(float* __restrict__ sW,
                                         const float* __restrict__ gW,
                                         int rowsUsed)
{
    for (int t = threadIdx.x; t < NC * KP; t += NTH) {
        int n  = t / KP;
        int kp = t - n * KP;
        int kl = (kp & ~7) | kinv(kp & 7);
        sW[t] = (kl < rowsUsed) ? f2tf32f(gW[kl * NC + n]) : 0.0f;
    }
}

// =====================================================================
// Unified MLP kernel (512 threads). One block = 128 rows = 128/SEG centers.
// buf2 aliases sIn. W2/W3 staged in chunks of KCH2/KCH3 rows.
// =====================================================================
template<int SEG, int C1, int C2, int C3, int KCH2, int KCH3>
__global__ __launch_bounds__(NTH) void mlp_mma_kernel(const float* __restrict__ xyz,
                                                      const float* __restrict__ points,
                                                      const int* __restrict__ idxbuf,
                                                      const float* __restrict__ W1, const float* __restrict__ B1,
                                                      const float* __restrict__ W2, const float* __restrict__ B2,
                                                      const float* __restrict__ W3, const float* __restrict__ B3,
                                                      float* __restrict__ outF)
{
    constexpr int CPB  = 128 / SEG;
    constexpr int S1   = KPAD(C1), S2 = KPAD(C2);
    constexpr int KP1  = KPAD(67);                 // 72
    constexpr int KP2  = KPAD(KCH2);
    constexpr int KP3  = KPAD(KCH3);
    constexpr int NCH2 = C1 / KCH2, NCH3 = C2 / KCH3;
    constexpr int REG0 = 128 * cmax2i(S_IN, S2);   // sIn region, reused as buf2
    constexpr int WMAX = cmax3i(C1 * KP1, C2 * KP2, C3 * KP3);
    constexpr int NT1  = C1 / 32, NT2 = C2 / 32, NT3 = C3 / 32;

    extern __shared__ float sm[];
    float* sIn   = sm;                  // [REG0] (later reused as buf2)
    float* buf1  = sm + REG0;           // 128 * S1
    float* sW    = buf1 + 128 * S1;     // WMAX
    int*   sMaxI = (int*)(sW + WMAX);   // 128
    int*   sIdx  = sMaxI + 128;         // 128

    int centerBase = blockIdx.x * CPB;
    int b = centerBase >> 10;

    for (int t = threadIdx.x; t < 128; t += NTH) {
        sIdx[t]  = idxbuf[(size_t)centerBase * SEG + t];
        sMaxI[t] = 0;
    }
    __syncthreads();

    const float* pB = points + (size_t)b * NPTS * CIN_PTS;
    const float* xB = xyz + (size_t)b * NPTS * 3;

    // gather input in permuted storage layout
    for (int t = threadIdx.x; t < 128 * S_IN; t += NTH) {
        int s   = t / S_IN;
        int cst = t - s * S_IN;
        int cl  = (cst & ~7) | kinv(cst & 7);    // logical column
        int ci  = centerBase + s / SEG;
        float v;
        if (cl < 64)       v = pB[(size_t)sIdx[s] * CIN_PTS + cl];
        else if (cl < 67) {
            int d = cl - 64;
            v = xB[(size_t)sIdx[s] * 3 + d] - g_new_xyz[ci * 3 + d];
        } else v = 0.0f;
        sIn[t] = f2tf32f(v);
    }
    stage_wt<C1, KP1>(sW, W1, 67);
    __syncthreads();

    // layer 1: sIn -> buf1 (K=67 staged whole, 9 k-steps)
    {
        float acc[2][NT1][4];
        #pragma unroll
        for (int mt = 0; mt < 2; mt++)
            #pragma unroll
            for (int nt = 0; nt < NT1; nt++)
                #pragma unroll
                for (int i = 0; i < 4; i++) acc[mt][nt][i] = 0.0f;
        mma_accum<9, S_IN, KP1, NT1>(sIn, 0, sW, acc);
        epi_relu<NT1, S1>(acc, B1, buf1);
    }
    __syncthreads();

    // layer 2: buf1 -> buf2 (aliases sIn). W2 [C1][C2], row stride C2.
    float* buf2 = sIn;
    {
        float acc[2][NT2][4];
        #pragma unroll
        for (int mt = 0; mt < 2; mt++)
            #pragma unroll
            for (int nt = 0; nt < NT2; nt++)
                #pragma unroll
                for (int i = 0; i < 4; i++) acc[mt][nt][i] = 0.0f;
        #pragma unroll
        for (int ch = 0; ch < NCH2; ch++) {
            stage_wt<C2, KP2>(sW, W2 + (size_t)ch * KCH2 * C2, KCH2);
            __syncthreads();
            mma_accum<KCH2 / 8, S1, KP2, NT2>(buf1, ch * KCH2, sW, acc);
            __syncthreads();
        }
        epi_relu<NT2, S2>(acc, B2, buf2);
    }
    __syncthreads();

    // layer 3: buf2 -> maxpool output. W3 [C2][C3], row stride C3  (BUGFIX: was *C2).
    {
        float acc[2][NT3][4];
        #pragma unroll
        for (int mt = 0; mt < 2; mt++)
            #pragma unroll
            for (int nt = 0; nt < NT3; nt++)
                #pragma unroll
                for (int i = 0; i < 4; i++) acc[mt][nt][i] = 0.0f;
        #pragma unroll
        for (int ch = 0; ch < NCH3; ch++) {
            stage_wt<C3, KP3>(sW, W3 + (size_t)ch * KCH3 * C3, KCH3);
            __syncthreads();
            mma_accum<KCH3 / 8, S2, KP3, NT3>(buf2, ch * KCH3, sW, acc);
            __syncthreads();
        }
        epi_final<NT3, SEG>(acc, B3, sMaxI, outF, centerBase);
    }

    if (SEG == 128) {
        __syncthreads();
        for (int t = threadIdx.x; t < C3; t += NTH)
            outF[(size_t)centerBase * FEAT_W + t] = __int_as_float(sMaxI[t]);
    }
}

// =====================================================================
// host launch
// =====================================================================
template<int SEG, int C1, int C2, int C3, int KCH2, int KCH3>
static constexpr int smem_mma() {
    constexpr int WMAX = cmax3i(C1 * KPAD(67), C2 * KPAD(KCH2), C3 * KPAD(KCH3));
    constexpr int REG0 = 128 * cmax2i(S_IN, KPAD(C2));
    return (REG0 + 128 * KPAD(C1) + WMAX + 256) * 4;
}

extern "C" void kernel_launch(void* const* d_in, const int* in_sizes, int n_in,
                              void* d_out, int out_size)
{
    const float* xyz = (const float*)d_in[0];
    const float* pts = (const float*)d_in[1];
    const float* W[3][3];
    const float* Bv[3][3];
    int k = 2;
    for (int bi = 0; bi < 3; bi++)
        for (int li = 0; li < 3; li++) {
            W[bi][li]  = (const float*)d_in[k++];
            Bv[bi][li] = (const float*)d_in[k++];
        }

    float* out        = (float*)d_out;
    float* out_newxyz = out;
    float* out_feat   = out + (size_t)NCENT * 3;

    const int fps_smem = 3 * NPTS * 4;
    const int bq_smem  = 3 * NPTS * 4;
    constexpr int sm0 = smem_mma<16, 32, 32, 64, 32, 32>();      //  68.6 KB -> 3/SM
    constexpr int sm1 = smem_mma<32, 64, 64, 128, 64, 32>();     //  95.2 KB -> 2/SM
    constexpr int sm2 = smem_mma<128, 64, 96, 128, 32, 24>();    // 109.6 KB -> 2/SM

    cudaFuncSetAttribute(fps_kernel, cudaFuncAttributeMaxDynamicSharedMemorySize, fps_smem);
    cudaFuncSetAttribute((const void*)mlp_mma_kernel<16, 32, 32, 64, 32, 32>,
                         cudaFuncAttributeMaxDynamicSharedMemorySize, sm0);
    cudaFuncSetAttribute((const void*)mlp_mma_kernel<32, 64, 64, 128, 64, 32>,
                         cudaFuncAttributeMaxDynamicSharedMemorySize, sm1);
    cudaFuncSetAttribute((const void*)mlp_mma_kernel<128, 64, 96, 128, 32, 24>,
                         cudaFuncAttributeMaxDynamicSharedMemorySize, sm2);

    fps_kernel<<<BATCH, 256, fps_smem>>>(xyz, out_newxyz);
    bq_fused_kernel<<<NCENT / 8, 256, bq_smem>>>(xyz, g_idx0, g_idx1, g_idx2);

    mlp_mma_kernel<128, 64, 96, 128, 32, 24><<<NCENT, NTH, sm2>>>(
        xyz, pts, g_idx2,
        W[2][0], Bv[2][0], W[2][1], Bv[2][1], W[2][2], Bv[2][2],
        out_feat + 192);
    mlp_mma_kernel<32, 64, 64, 128, 64, 32><<<NCENT / 4, NTH, sm1>>>(
        xyz, pts, g_idx1,
        W[1][0], Bv[1][0], W[1][1], Bv[1][1], W[1][2], Bv[1][2],
        out_feat + 64);
    mlp_mma_kernel<16, 32, 32, 64, 32, 32><<<NCENT / 8, NTH, sm0>>>(
        xyz, pts, g_idx0,
        W[0][0], Bv[0][0], W[0][1], Bv[0][1], W[0][2], Bv[0][2],
        out_feat + 0);
}

// round 10
// speedup vs baseline: 1.2139x; 1.2139x over previous
#include <cuda_runtime.h>
#include <cuda_bf16.h>
#include <cstdint>

#define BATCH   8
#define NPTS    4096
#define CIN_PTS 64
#define NPOINT  1024
#define NCENT   (BATCH * NPOINT)   // 8192
#define FEAT_W  320
#define S_IN    76                 // input stride: 67 used + zero pad
#define NTH     512                // threads per MLP block

// ---------------- device scratch ----------------
__device__ float g_new_xyz[NCENT * 3];
__device__ int   g_idx0[NCENT * 16];
__device__ int   g_idx1[NCENT * 32];
__device__ int   g_idx2[NCENT * 128];

__host__ __device__ constexpr int cmax3i(int a, int b, int c) {
    return a > b ? (a > c ? a : c) : (b > c ? b : c);
}
__host__ __device__ constexpr int cmax2i(int a, int b) { return a > b ? a : b; }

// =====================================================================
// FPS: one block per batch, 256 threads x 16 register-resident points.
// Per-thread 16->1 tournament tree (short dependency chain), warp
// shuffle reduce, rotating 3-slot 64-bit atomicMax key (JAX tie-break).
// =====================================================================
__global__ __launch_bounds__(256) void fps_kernel(const float* __restrict__ xyz,
                                                  float* __restrict__ out_newxyz)
{
    int b = blockIdx.x;
    extern __shared__ float sm[];
    float* sx = sm;
    float* sy = sm + NPTS;
    float* sz = sm + 2 * NPTS;
    __shared__ unsigned long long skey[3];

    const float* base = xyz + (size_t)b * NPTS * 3;
    float px[16], py[16], pz[16], pd[16];
    #pragma unroll
    for (int r = 0; r < 16; r++) {
        int p = threadIdx.x + r * 256;
        float x = base[p * 3 + 0];
        float y = base[p * 3 + 1];
        float z = base[p * 3 + 2];
        sx[p] = x; sy[p] = y; sz[p] = z;
        px[r] = x; py[r] = y; pz[r] = z;
        pd[r] = 1e10f;
    }
    if (threadIdx.x == 0) {
        skey[0] = 0xFFFFFFFFull;   // decodes to index 0
        skey[1] = 0ull;
        skey[2] = 0ull;
    }
    __syncthreads();

    int lane = threadIdx.x & 31;

    for (int it = 0; it < NPOINT; it++) {
        int cur = it % 3, nxt = (it + 1) % 3, rst = (it + 2) % 3;
        unsigned int low = (unsigned int)skey[cur];
        int far = (int)(0xFFFFFFFFu - low);

        if (threadIdx.x == 0) {
            float fx = sx[far], fy = sy[far], fz = sz[far];
            int row = b * NPOINT + it;
            out_newxyz[row * 3 + 0] = fx;
            out_newxyz[row * 3 + 1] = fy;
            out_newxyz[row * 3 + 2] = fz;
            g_new_xyz[row * 3 + 0] = fx;
            g_new_xyz[row * 3 + 1] = fy;
            g_new_xyz[row * 3 + 2] = fz;
            skey[rst] = 0ull;
        }
        float cx = sx[far], cy = sy[far], cz = sz[far];

        // distances + min-update (independent per r -> full ILP)
        float nv[16];
        #pragma unroll
        for (int r = 0; r < 16; r++) {
            float dx = px[r] - cx;
            float dy = py[r] - cy;
            float dz = pz[r] - cz;
            float d = __fadd_rn(__fadd_rn(__fmul_rn(dx, dx), __fmul_rn(dy, dy)),
                                __fmul_rn(dz, dz));
            float nd = fminf(pd[r], d);
            pd[r] = nd;
            nv[r] = nd;
        }
        // tournament 16->8->4->2->1. Left operand always holds the smaller
        // point index, so '>=' preserves first-index tie-break exactly.
        float v8[8]; int i8[8];
        #pragma unroll
        for (int j = 0; j < 8; j++) {
            bool a = nv[2 * j] >= nv[2 * j + 1];
            v8[j] = a ? nv[2 * j] : nv[2 * j + 1];
            i8[j] = a ? 2 * j : 2 * j + 1;
        }
        float v4[4]; int i4[4];
        #pragma unroll
        for (int j = 0; j < 4; j++) {
            bool a = v8[2 * j] >= v8[2 * j + 1];
            v4[j] = a ? v8[2 * j] : v8[2 * j + 1];
            i4[j] = a ? i8[2 * j] : i8[2 * j + 1];
        }
        float v2[2]; int i2[2];
        #pragma unroll
        for (int j = 0; j < 2; j++) {
            bool a = v4[2 * j] >= v4[2 * j + 1];
            v2[j] = a ? v4[2 * j] : v4[2 * j + 1];
            i2[j] = a ? i4[2 * j] : i4[2 * j + 1];
        }
        bool a0 = v2[0] >= v2[1];
        float bv = a0 ? v2[0] : v2[1];
        int   br = a0 ? i2[0] : i2[1];
        int   bi = threadIdx.x + br * 256;

        // warp reduce (max value, smallest index on tie)
        #pragma unroll
        for (int off = 16; off >= 1; off >>= 1) {
            float ov = __shfl_down_sync(0xffffffffu, bv, off);
            int   oi = __shfl_down_sync(0xffffffffu, bi, off);
            if (ov > bv || (ov == bv && oi < bi)) { bv = ov; bi = oi; }
        }
        if (lane == 0) {
            unsigned long long key =
                ((unsigned long long)__float_as_uint(bv) << 32) |
                (unsigned long long)(0xFFFFFFFFu - (unsigned int)bi);
            atomicMax(&skey[nxt], key);
        }
        __syncthreads();
    }
}

// =====================================================================
// Fused ball query (3 radii, one smem-staged scan). Warp per center.
// =====================================================================
__global__ __launch_bounds__(256) void bq_fused_kernel(const float* __restrict__ xyz,
                                                       int* __restrict__ o0,
                                                       int* __restrict__ o1,
                                                       int* __restrict__ o2)
{
    extern __shared__ float sm[];
    float* sx = sm;
    float* sy = sm + NPTS;
    float* sz = sm + 2 * NPTS;

    int wid  = threadIdx.x >> 5;
    int lane = threadIdx.x & 31;
    int gw   = blockIdx.x * 8 + wid;
    int b    = gw >> 10;

    const float* base = xyz + (size_t)b * NPTS * 3;
    for (int t = threadIdx.x; t < NPTS * 3; t += 256) {
        int p = t / 3, c = t - p * 3;
        float v = base[t];
        (c == 0 ? sx : (c == 1 ? sy : sz))[p] = v;
    }
    __syncthreads();

    const float r2_0 = (float)(0.1 * 0.1);
    const float r2_1 = (float)(0.2 * 0.2);
    const float r2_2 = (float)(0.4 * 0.4);

    float cx = g_new_xyz[gw * 3 + 0];
    float cy = g_new_xyz[gw * 3 + 1];
    float cz = g_new_xyz[gw * 3 + 2];

    int* p0 = o0 + (size_t)gw * 16;
    int* p1 = o1 + (size_t)gw * 32;
    int* p2 = o2 + (size_t)gw * 128;

    int c0 = 0, c1 = 0, c2 = 0;
    int f0 = -1, f1 = -1, f2 = -1;
    unsigned lmask = (1u << lane) - 1u;

    for (int s = 0; s < NPTS; s += 32) {
        int p = s + lane;
        float dx = sx[p] - cx;
        float dy = sy[p] - cy;
        float dz = sz[p] - cz;
        float d2 = __fadd_rn(__fadd_rn(__fmul_rn(dx, dx), __fmul_rn(dy, dy)),
                             __fmul_rn(dz, dz));
        bool h0 = d2 < r2_0, h1 = d2 < r2_1, h2 = d2 < r2_2;
        unsigned m0 = __ballot_sync(0xffffffffu, h0);
        unsigned m1 = __ballot_sync(0xffffffffu, h1);
        unsigned m2 = __ballot_sync(0xffffffffu, h2);
        if (m0) {
            if (f0 < 0) f0 = s + (__ffs(m0) - 1);
            if (h0) { int pos = c0 + __popc(m0 & lmask); if (pos < 16) p0[pos] = p; }
            c0 += __popc(m0);
        }
        if (m1) {
            if (f1 < 0) f1 = s + (__ffs(m1) - 1);
            if (h1) { int pos = c1 + __popc(m1 & lmask); if (pos < 32) p1[pos] = p; }
            c1 += __popc(m1);
        }
        if (m2) {
            if (f2 < 0) f2 = s + (__ffs(m2) - 1);
            if (h2) { int pos = c2 + __popc(m2 & lmask); if (pos < 128) p2[pos] = p; }
            c2 += __popc(m2);
        }
        if (c0 >= 16 && c1 >= 32 && c2 >= 128) break;
    }
    for (int pos = c0 + lane; pos < 16; pos += 32) p0[pos] = f0;
    for (int pos = c1 + lane; pos < 32; pos += 32) p1[pos] = f1;
    for (int pos = c2 + lane; pos < 128; pos += 32) p2[pos] = f2;
}

// =====================================================================
// tf32 mma building blocks. 512 threads: 4 m-warps (w>>2) x 4 n-warps (w&3).
// =====================================================================
__device__ __forceinline__ uint32_t f2tf32(float f) {
    uint32_t r; asm("cvt.rna.tf32.f32 %0, %1;" : "=r"(r) : "f"(f)); return r;
}

__device__ __forceinline__ void mma_tf32(float* d, const uint32_t* a, const uint32_t* b) {
    asm volatile("mma.sync.aligned.m16n8k8.row.col.f32.tf32.tf32.f32 "
                 "{%0,%1,%2,%3},{%4,%5,%6,%7},{%8,%9},{%0,%1,%2,%3};"
                 : "+f"(d[0]), "+f"(d[1]), "+f"(d[2]), "+f"(d[3])
                 : "r"(a[0]), "r"(a[1]), "r"(a[2]), "r"(a[3]),
                   "r"(b[0]), "r"(b[1]));
}

// A rows m0..m0+31 (per warp), A column offset kOff, staged W rows 0..KSTEPS*8-1.
template<int KSTEPS, int SA, int NP, int NT>
__device__ __forceinline__ void mma_accum(const float* __restrict__ sA, int kOff,
                                          const float* __restrict__ sW,
                                          float (&acc)[2][NT][4])
{
    int lane = threadIdx.x & 31;
    int w    = threadIdx.x >> 5;
    int g    = lane >> 2;
    int tg   = lane & 3;
    int m0   = (w >> 2) * 32;
    int n0   = (w & 3) * (NT * 8);

    for (int ks = 0; ks < KSTEPS; ks++) {
        int k0 = ks * 8;
        uint32_t a[2][4];
        #pragma unroll
        for (int mt = 0; mt < 2; mt++) {
            const float* Ab = sA + (m0 + 16 * mt) * SA + kOff + k0;
            a[mt][0] = f2tf32(Ab[g * SA + tg]);
            a[mt][1] = f2tf32(Ab[(g + 8) * SA + tg]);
            a[mt][2] = f2tf32(Ab[g * SA + tg + 4]);
            a[mt][3] = f2tf32(Ab[(g + 8) * SA + tg + 4]);
        }
        #pragma unroll
        for (int nt = 0; nt < NT; nt++) {
            const float* Wb = sW + k0 * NP + n0 + 8 * nt;
            uint32_t bfr[2];
            bfr[0] = f2tf32(Wb[tg * NP + g]);
            bfr[1] = f2tf32(Wb[(tg + 4) * NP + g]);
            mma_tf32(acc[0][nt], a[0], bfr);
            mma_tf32(acc[1][nt], a[1], bfr);
        }
    }
}

template<int NT, int SOUT>
__device__ __forceinline__ void epi_relu(float (&acc)[2][NT][4],
                                         const float* __restrict__ gBias,
                                         float* __restrict__ sOut)
{
    int lane = threadIdx.x & 31;
    int w    = threadIdx.x >> 5;
    int g    = lane >> 2;
    int tg   = lane & 3;
    int m0   = (w >> 2) * 32;
    int n0   = (w & 3) * (NT * 8);
    #pragma unroll
    for (int mt = 0; mt < 2; mt++)
        #pragma unroll
        for (int nt = 0; nt < NT; nt++) {
            int row = m0 + 16 * mt + g;
            int col = n0 + 8 * nt + 2 * tg;
            float b0v = gBias[col], b1v = gBias[col + 1];
            sOut[row * SOUT + col]           = fmaxf(acc[mt][nt][0] + b0v, 0.0f);
            sOut[row * SOUT + col + 1]       = fmaxf(acc[mt][nt][1] + b1v, 0.0f);
            sOut[(row + 8) * SOUT + col]     = fmaxf(acc[mt][nt][2] + b0v, 0.0f);
            sOut[(row + 8) * SOUT + col + 1] = fmaxf(acc[mt][nt][3] + b1v, 0.0f);
        }
}

template<int NT, int SEG>
__device__ __forceinline__ void epi_final(float (&acc)[2][NT][4],
                                          const float* __restrict__ gBias,
                                          int* __restrict__ sMaxI,
                                          float* __restrict__ outF, int centerBase)
{
    int lane = threadIdx.x & 31;
    int w    = threadIdx.x >> 5;
    int g    = lane >> 2;
    int tg   = lane & 3;
    int n0   = (w & 3) * (NT * 8);

    if (SEG == 128) {
        #pragma unroll
        for (int nt = 0; nt < NT; nt++) {
            int col = n0 + 8 * nt + 2 * tg;
            float v0 = fmaxf(fmaxf(acc[0][nt][0], acc[0][nt][2]),
                             fmaxf(acc[1][nt][0], acc[1][nt][2]));
            float v1 = fmaxf(fmaxf(acc[0][nt][1], acc[0][nt][3]),
                             fmaxf(acc[1][nt][1], acc[1][nt][3]));
            v0 = fmaxf(v0 + gBias[col], 0.0f);
            v1 = fmaxf(v1 + gBias[col + 1], 0.0f);
            #pragma unroll
            for (int off = 4; off < 32; off <<= 1) {
                v0 = fmaxf(v0, __shfl_xor_sync(0xffffffffu, v0, off));
                v1 = fmaxf(v1, __shfl_xor_sync(0xffffffffu, v1, off));
            }
            if (g == 0) {
                atomicMax(&sMaxI[col],     __float_as_int(v0));
                atomicMax(&sMaxI[col + 1], __float_as_int(v1));
            }
        }
    } else if (SEG == 32) {
        int center = centerBase + (w >> 2);
        #pragma unroll
        for (int nt = 0; nt < NT; nt++) {
            int col = n0 + 8 * nt + 2 * tg;
            float v0 = fmaxf(fmaxf(acc[0][nt][0], acc[0][nt][2]),
                             fmaxf(acc[1][nt][0], acc[1][nt][2]));
            float v1 = fmaxf(fmaxf(acc[0][nt][1], acc[0][nt][3]),
                             fmaxf(acc[1][nt][1], acc[1][nt][3]));
            #pragma unroll
            for (int off = 4; off < 32; off <<= 1) {
                v0 = fmaxf(v0, __shfl_xor_sync(0xffffffffu, v0, off));
                v1 = fmaxf(v1, __shfl_xor_sync(0xffffffffu, v1, off));
            }
            if (g == 0) {
                float* op = outF + (size_t)center * FEAT_W;
                op[col]     = fmaxf(v0 + gBias[col], 0.0f);
                op[col + 1] = fmaxf(v1 + gBias[col + 1], 0.0f);
            }
        }
    } else { // SEG == 16: each m-tile (mt) is one center
        #pragma unroll
        for (int mt = 0; mt < 2; mt++) {
            int center = centerBase + (w >> 2) * 2 + mt;
            #pragma unroll
            for (int nt = 0; nt < NT; nt++) {
                int col = n0 + 8 * nt + 2 * tg;
                float v0 = fmaxf(acc[mt][nt][0], acc[mt][nt][2]);
                float v1 = fmaxf(acc[mt][nt][1], acc[mt][nt][3]);
                #pragma unroll
                for (int off = 4; off < 32; off <<= 1) {
                    v0 = fmaxf(v0, __shfl_xor_sync(0xffffffffu, v0, off));
                    v1 = fmaxf(v1, __shfl_xor_sync(0xffffffffu, v1, off));
                }
                if (g == 0) {
                    float* op = outF + (size_t)center * FEAT_W;
                    op[col]     = fmaxf(v0 + gBias[col], 0.0f);
                    op[col + 1] = fmaxf(v1 + gBias[col + 1], 0.0f);
                }
            }
        }
    }
}

template<int ROWS, int KR, int NC, int NP>
__device__ __forceinline__ void stage_w(float* __restrict__ sW, const float* __restrict__ gW)
{
    for (int t = threadIdx.x; t < ROWS * NP; t += NTH) {
        int r = t / NP, c = t - r * NP;
        sW[t] = (r < KR && c < NC) ? gW[r * NC + c] : 0.0f;
    }
}

// =====================================================================
// Unified MLP kernel (512 threads). One block = 128 rows.
// buf2 aliases sIn (dead after layer 1). W3 staged in chunks for C2==96.
// =====================================================================
template<int SEG, int C1, int C2, int C3>
__global__ __launch_bounds__(NTH) void mlp_mma_kernel(const float* __restrict__ xyz,
                                                      const float* __restrict__ points,
                                                      const int* __restrict__ idxbuf,
                                                      const float* __restrict__ W1, const float* __restrict__ B1,
                                                      const float* __restrict__ W2, const float* __restrict__ B2,
                                                      const float* __restrict__ W3, const float* __restrict__ B3,
                                                      float* __restrict__ outF)
{
    constexpr int CPB  = 128 / SEG;
    constexpr int S1   = C1 + 4, S2 = C2 + 4;
    constexpr int NP1  = C1 + 8, NP2 = C2 + 8, NP3 = C3 + 8;
    constexpr int W3CH = (C2 == 96) ? 48 : C2;   // W3 staging chunk rows
    constexpr int NCH  = C2 / W3CH;
    constexpr int REG0 = 128 * cmax2i(S_IN, S2); // sIn region, reused as buf2
    constexpr int WMAX = cmax3i(72 * NP1, C1 * NP2, W3CH * NP3);
    constexpr int KS2  = C1 / 8;
    constexpr int NT1  = C1 / 32, NT2 = C2 / 32, NT3 = C3 / 32;

    extern __shared__ float sm[];
    float* sIn   = sm;                  // [REG0] (later reused as buf2)
    float* buf1  = sm + REG0;           // 128 * S1
    float* sW    = buf1 + 128 * S1;     // WMAX
    int*   sMaxI = (int*)(sW + WMAX);   // 128
    int*   sIdx  = sMaxI + 128;         // 128

    int centerBase = blockIdx.x * CPB;
    int b = centerBase >> 10;

    for (int t = threadIdx.x; t < 128; t += NTH) {
        sIdx[t]  = idxbuf[(size_t)centerBase * SEG + t];
        sMaxI[t] = 0;
    }
    __syncthreads();

    const float* pB = points + (size_t)b * NPTS * CIN_PTS;
    const float* xB = xyz + (size_t)b * NPTS * 3;

    for (int t = threadIdx.x; t < 128 * S_IN; t += NTH) {
        int s = t / S_IN, c = t - s * S_IN;
        int ci = centerBase + s / SEG;
        float v;
        if (c < 64)       v = pB[(size_t)sIdx[s] * CIN_PTS + c];
        else if (c < 67) {
            int d = c - 64;
            v = xB[(size_t)sIdx[s] * 3 + d] - g_new_xyz[ci * 3 + d];
        } else v = 0.0f;
        sIn[t] = v;
    }
    stage_w<72, 67, C1, NP1>(sW, W1);
    __syncthreads();

    // layer 1: sIn -> buf1
    {
        float acc[2][NT1][4];
        #pragma unroll
        for (int mt = 0; mt < 2; mt++)
            #pragma unroll
            for (int nt = 0; nt < NT1; nt++)
                #pragma unroll
                for (int i = 0; i < 4; i++) acc[mt][nt][i] = 0.0f;
        mma_accum<9, S_IN, NP1, NT1>(sIn, 0, sW, acc);
        epi_relu<NT1, S1>(acc, B1, buf1);
    }
    __syncthreads();

    stage_w<C1, C1, C2, NP2>(sW, W2);
    __syncthreads();

    // layer 2: buf1 -> buf2 (aliases sIn; sIn fully consumed in layer 1)
    float* buf2 = sIn;
    {
        float acc[2][NT2][4];
        #pragma unroll
        for (int mt = 0; mt < 2; mt++)
            #pragma unroll
            for (int nt = 0; nt < NT2; nt++)
                #pragma unroll
                for (int i = 0; i < 4; i++) acc[mt][nt][i] = 0.0f;
        mma_accum<KS2, S1, NP2, NT2>(buf1, 0, sW, acc);
        epi_relu<NT2, S2>(acc, B2, buf2);
    }
    __syncthreads();

    // layer 3: buf2 -> maxpool output. W3 [C2][C3] staged in NCH chunks.
    {
        float acc[2][NT3][4];
        #pragma unroll
        for (int mt = 0; mt < 2; mt++)
            #pragma unroll
            for (int nt = 0; nt < NT3; nt++)
                #pragma unroll
                for (int i = 0; i < 4; i++) acc[mt][nt][i] = 0.0f;
        for (int ch = 0; ch < NCH; ch++) {
            stage_w<W3CH, W3CH, C3, NP3>(sW, W3 + (size_t)ch * W3CH * C3);
            __syncthreads();
            mma_accum<W3CH / 8, S2, NP3, NT3>(buf2, ch * W3CH, sW, acc);
            __syncthreads();
        }
        epi_final<NT3, SEG>(acc, B3, sMaxI, outF, centerBase);
    }

    if (SEG == 128) {
        __syncthreads();
        for (int t = threadIdx.x; t < C3; t += NTH)
            outF[(size_t)centerBase * FEAT_W + t] = __int_as_float(sMaxI[t]);
    }
}

// =====================================================================
// host launch
// =====================================================================
template<int SEG, int C1, int C2, int C3>
static constexpr int smem_mma() {
    constexpr int S2 = C2 + 4;
    constexpr int W3CH = (C2 == 96) ? 48 : C2;
    constexpr int WMAX = cmax3i(72 * (C1 + 8), C1 * (C2 + 8), W3CH * (C3 + 8));
    constexpr int REG0 = 128 * cmax2i(S_IN, S2);
    return (REG0 + 128 * (C1 + 4) + WMAX + 256) * 4;
}

extern "C" void kernel_launch(void* const* d_in, const int* in_sizes, int n_in,
                              void* d_out, int out_size)
{
    const float* xyz = (const float*)d_in[0];
    const float* pts = (const float*)d_in[1];
    const float* W[3][3];
    const float* Bv[3][3];
    int k = 2;
    for (int bi = 0; bi < 3; bi++)
        for (int li = 0; li < 3; li++) {
            W[bi][li]  = (const float*)d_in[k++];
            Bv[bi][li] = (const float*)d_in[k++];
        }

    float* out        = (float*)d_out;
    float* out_newxyz = out;
    float* out_feat   = out + (size_t)NCENT * 3;

    const int fps_smem = 3 * NPTS * 4;
    const int bq_smem  = 3 * NPTS * 4;
    constexpr int sm0 = smem_mma<16, 32, 32, 64>();     //  69,888 B -> 3 blocks/SM
    constexpr int sm1 = smem_mma<32, 64, 64, 128>();    // 109,568 B -> 2 blocks/SM
    constexpr int sm2 = smem_mma<128, 64, 96, 128>();   // 113,664 B -> 2 blocks/SM

    cudaFuncSetAttribute(fps_kernel, cudaFuncAttributeMaxDynamicSharedMemorySize, fps_smem);
    cudaFuncSetAttribute((const void*)mlp_mma_kernel<16, 32, 32, 64>,
                         cudaFuncAttributeMaxDynamicSharedMemorySize, sm0);
    cudaFuncSetAttribute((const void*)mlp_mma_kernel<32, 64, 64, 128>,
                         cudaFuncAttributeMaxDynamicSharedMemorySize, sm1);
    cudaFuncSetAttribute((const void*)mlp_mma_kernel<128, 64, 96, 128>,
                         cudaFuncAttributeMaxDynamicSharedMemorySize, sm2);

    fps_kernel<<<BATCH, 256, fps_smem>>>(xyz, out_newxyz);
    bq_fused_kernel<<<NCENT / 8, 256, bq_smem>>>(xyz, g_idx0, g_idx1, g_idx2);

    mlp_mma_kernel<128, 64, 96, 128><<<NCENT, NTH, sm2>>>(
        xyz, pts, g_idx2,
        W[2][0], Bv[2][0], W[2][1], Bv[2][1], W[2][2], Bv[2][2],
        out_feat + 192);
    mlp_mma_kernel<32, 64, 64, 128><<<NCENT / 4, NTH, sm1>>>(
        xyz, pts, g_idx1,
        W[1][0], Bv[1][0], W[1][1], Bv[1][1], W[1][2], Bv[1][2],
        out_feat + 64);
    mlp_mma_kernel<16, 32, 32, 64><<<NCENT / 8, NTH, sm0>>>(
        xyz, pts, g_idx0,
        W[0][0], Bv[0][0], W[0][1], Bv[0][1], W[0][2], Bv[0][2],
        out_feat + 0);
}